// round 1
// baseline (speedup 1.0000x reference)
#include <cuda_runtime.h>
#include <math.h>

// Problem constants
#define Hd 512      // hidden size (rows of h)
#define Bd 1024     // batch (cols of h)
#define Td 512      // timesteps
#define Od 10       // output size
#define RT 64       // rows per CTA tile
#define CT 64       // batch cols per CTA tile
#define KC 64       // K-chunk staged in SMEM
#define ROWT (Hd/RT)   // 8
#define COLT (Bd/CT)   // 16
#define NCTA (ROWT*COLT)  // 128 CTAs (<= 148 SMs, all co-resident)

// Persistent scratch: ping-pong hidden state buffers (no runtime allocation allowed)
__device__ float g_h[2][Hd * Bd];
__device__ unsigned g_bar_count = 0;
__device__ unsigned g_bar_gen   = 0;

__device__ __forceinline__ void grid_barrier() {
    __syncthreads();
    __threadfence();   // make this thread's global writes visible before arrival
    if (threadIdx.x == 0) {
        unsigned gen = *((volatile unsigned*)&g_bar_gen);
        unsigned ticket = atomicAdd(&g_bar_count, 1u);
        if (ticket == NCTA - 1) {
            g_bar_count = 0;
            __threadfence();
            atomicAdd(&g_bar_gen, 1u);
        } else {
            while (*((volatile unsigned*)&g_bar_gen) == gen) { __nanosleep(32); }
        }
    }
    __syncthreads();
}

extern __shared__ float smem[];

__global__ void __launch_bounds__(256, 1)
rnn_persistent_kernel(const float* __restrict__ x,
                      const float* __restrict__ W_hx,
                      const float* __restrict__ W_hh,
                      const float* __restrict__ W_yh,
                      const float* __restrict__ b_h,
                      const float* __restrict__ b_y,
                      float* __restrict__ out)
{
    // SMEM layout
    float* Ws = smem;                       // [512][64]  W_hh tile, k-major  (128 KB)
    float* Hs = smem + Hd * RT;             // [2][64][64] h chunk double-buffer (32 KB)
    float* xs = Hs + 2 * KC * CT;           // [64] x values for this step

    const int tid = threadIdx.x;
    const int tx  = tid & 15;
    const int ty  = tid >> 4;
    const int tx4 = tx * 4;
    const int ty4 = ty * 4;
    const int rt  = blockIdx.x >> 4;        // 0..7
    const int ct  = blockIdx.x & 15;        // 0..15
    const int r0  = rt * RT;
    const int c0  = ct * CT;

    // --- Load W_hh tile into SMEM once (k-major: Ws[k][r]) ---
    // Consecutive tid -> consecutive r: conflict-free STS; global reads hit L1
    // lines repeatedly across the k sweep (each 128B line used 8x).
    for (int idx = tid; idx < Hd * RT; idx += 256) {
        int k = idx >> 6;      // 0..511 (4 k-values per 256-thread pass)
        int r = idx & 63;
        Ws[k * RT + r] = W_hh[(r0 + r) * Hd + k];
    }

    // Per-thread row parameters (fixed rows for whole run)
    float whx[4], bh[4];
#pragma unroll
    for (int i = 0; i < 4; ++i) {
        whx[i] = W_hx[r0 + ty4 + i];
        bh[i]  = b_h[r0 + ty4 + i];
    }

    // --- Zero h0 (buffer 0), partitioned across CTAs ---
    {
        float4 z = make_float4(0.f, 0.f, 0.f, 0.f);
        float4* hb = (float4*)g_h[0];
        int base = blockIdx.x * 1024;       // 131072 float4 total / 128 CTAs
#pragma unroll
        for (int p = 0; p < 4; ++p)
            hb[base + tid + p * 256] = z;
    }
    grid_barrier();

    int buf = 0;
    for (int t = 0; t < Td; ++t) {
        const float* __restrict__ hin  = g_h[buf];
        float* __restrict__       hout = g_h[buf ^ 1];

        if (tid < CT) xs[tid] = __ldg(&x[(c0 + tid) * Td + t]);

        float acc[4][4];
#pragma unroll
        for (int i = 0; i < 4; ++i)
#pragma unroll
            for (int j = 0; j < 4; ++j) acc[i][j] = 0.f;

        // Prefetch chunk 0 into registers (L2-only loads: h is cross-SM data)
        float4 pf[4];
#pragma unroll
        for (int p = 0; p < 4; ++p) {
            int f  = tid + p * 256;         // float4 index in chunk [64 x 16]
            int kk = f >> 4;
            int c4 = f & 15;
            pf[p] = __ldcg((const float4*)&hin[kk * Bd + c0 + c4 * 4]);
        }

        for (int c = 0; c < 8; ++c) {
            float* hsb = Hs + (c & 1) * (KC * CT);
#pragma unroll
            for (int p = 0; p < 4; ++p) {
                int f  = tid + p * 256;
                int kk = f >> 4;
                int c4 = f & 15;
                *(float4*)&hsb[kk * CT + c4 * 4] = pf[p];
            }
            __syncthreads();   // hsb ready; prior compute on this buffer finished 2 chunks ago

            if (c < 7) {
                int k0n = (c + 1) * KC;
#pragma unroll
                for (int p = 0; p < 4; ++p) {
                    int f  = tid + p * 256;
                    int kk = f >> 4;
                    int c4 = f & 15;
                    pf[p] = __ldcg((const float4*)&hin[(k0n + kk) * Bd + c0 + c4 * 4]);
                }
            }

            const float* wbase = Ws + (c * KC) * RT;
#pragma unroll 8
            for (int kk = 0; kk < KC; ++kk) {
                float4 wv = *(const float4*)&wbase[kk * RT + ty4];
                float4 hv = *(const float4*)&hsb[kk * CT + tx4];
                acc[0][0] += wv.x * hv.x;  acc[0][1] += wv.x * hv.y;
                acc[0][2] += wv.x * hv.z;  acc[0][3] += wv.x * hv.w;
                acc[1][0] += wv.y * hv.x;  acc[1][1] += wv.y * hv.y;
                acc[1][2] += wv.y * hv.z;  acc[1][3] += wv.y * hv.w;
                acc[2][0] += wv.z * hv.x;  acc[2][1] += wv.z * hv.y;
                acc[2][2] += wv.z * hv.z;  acc[2][3] += wv.z * hv.w;
                acc[3][0] += wv.w * hv.x;  acc[3][1] += wv.w * hv.y;
                acc[3][2] += wv.w * hv.z;  acc[3][3] += wv.w * hv.w;
            }
            // No second sync needed: next chunk's STS targets the other buffer.
        }

        // Epilogue: h_new = tanh(acc + W_hx[r]*x[b,t] + b_h[r]), write ping-pong buffer
        float xv0 = xs[tx4 + 0], xv1 = xs[tx4 + 1], xv2 = xs[tx4 + 2], xv3 = xs[tx4 + 3];
#pragma unroll
        for (int i = 0; i < 4; ++i) {
            int r = r0 + ty4 + i;
            float4 o;
            o.x = tanhf(acc[i][0] + whx[i] * xv0 + bh[i]);
            o.y = tanhf(acc[i][1] + whx[i] * xv1 + bh[i]);
            o.z = tanhf(acc[i][2] + whx[i] * xv2 + bh[i]);
            o.w = tanhf(acc[i][3] + whx[i] * xv3 + bh[i]);
            *(float4*)&hout[r * Bd + c0 + tx4] = o;
        }

        buf ^= 1;
        grid_barrier();   // publishes hout to all CTAs
    }

    // --- Final projection: out[b][o] = b_y[o] + sum_k W_yh[o][k] * h_T[k][b] ---
    // After 512 flips, final h is in g_h[buf] (buf == 0). Only rt==0 CTAs work.
    if (rt == 0) {
        const float* __restrict__ hf = g_h[buf];
        for (int idx = tid; idx < Od * CT; idx += 256) {
            int o  = idx >> 6;          // 0..9
            int cc = idx & 63;
            int b  = c0 + cc;
            float acc2 = b_y[o];
            const float* wrow = W_yh + o * Hd;
#pragma unroll 4
            for (int k = 0; k < Hd; ++k)
                acc2 += wrow[k] * __ldcg(&hf[k * Bd + b]);
            out[b * Od + o] = acc2;
        }
    }
}

extern "C" void kernel_launch(void* const* d_in, const int* in_sizes, int n_in,
                              void* d_out, int out_size) {
    (void)in_sizes; (void)n_in; (void)out_size;
    const float* x    = (const float*)d_in[0];
    const float* W_hx = (const float*)d_in[1];
    const float* W_hh = (const float*)d_in[2];
    const float* W_yh = (const float*)d_in[3];
    const float* b_h  = (const float*)d_in[4];
    const float* b_y  = (const float*)d_in[5];
    float* out = (float*)d_out;

    const int smem_bytes = (Hd * RT + 2 * KC * CT + CT) * (int)sizeof(float); // ~164 KB
    cudaFuncSetAttribute(rnn_persistent_kernel,
                         cudaFuncAttributeMaxDynamicSharedMemorySize, smem_bytes);

    rnn_persistent_kernel<<<NCTA, 256, smem_bytes>>>(x, W_hx, W_hh, W_yh, b_h, b_y, out);
}

// round 2
// speedup vs baseline: 1.0038x; 1.0038x over previous
#include <cuda_runtime.h>
#include <math.h>

// Problem constants
#define Hd 512      // hidden size (rows of h)
#define Bd 1024     // batch (cols of h)
#define Td 512      // timesteps
#define Od 10       // output size
#define RT 64       // rows per CTA tile
#define CT 64       // batch cols per CTA tile
#define KC 64       // K-chunk staged in SMEM
#define ROWT (Hd/RT)   // 8
#define COLT (Bd/CT)   // 16
#define NCTA (ROWT*COLT)  // 128 CTAs (<= 148 SMs, all co-resident)

// Persistent scratch: ping-pong hidden state buffers (no runtime allocation allowed)
__device__ float g_h[2][Hd * Bd];
__device__ unsigned g_bar_count = 0;
__device__ unsigned g_bar_gen   = 0;

__device__ __forceinline__ void grid_barrier() {
    __syncthreads();
    __threadfence();   // make this thread's global writes visible before arrival
    if (threadIdx.x == 0) {
        unsigned gen = *((volatile unsigned*)&g_bar_gen);
        unsigned ticket = atomicAdd(&g_bar_count, 1u);
        if (ticket == NCTA - 1) {
            g_bar_count = 0;
            __threadfence();
            atomicAdd(&g_bar_gen, 1u);
        } else {
            while (*((volatile unsigned*)&g_bar_gen) == gen) { __nanosleep(32); }
        }
    }
    __syncthreads();
}

extern __shared__ float smem[];

__global__ void __launch_bounds__(256, 1)
rnn_persistent_kernel(const float* __restrict__ x,
                      const float* __restrict__ W_hx,
                      const float* __restrict__ W_hh,
                      const float* __restrict__ W_yh,
                      const float* __restrict__ b_h,
                      const float* __restrict__ b_y,
                      float* __restrict__ out)
{
    // SMEM layout
    float* Ws = smem;                       // [512][64]  W_hh tile, k-major  (128 KB)
    float* Hs = smem + Hd * RT;             // [2][64][64] h chunk double-buffer (32 KB)
    float* xs = Hs + 2 * KC * CT;           // [64] x values for this step

    const int tid = threadIdx.x;
    const int tx  = tid & 15;
    const int ty  = tid >> 4;
    const int tx4 = tx * 4;
    const int ty4 = ty * 4;
    const int rt  = blockIdx.x >> 4;        // 0..7
    const int ct  = blockIdx.x & 15;        // 0..15
    const int r0  = rt * RT;
    const int c0  = ct * CT;

    // --- Load W_hh tile into SMEM once (k-major: Ws[k][r]) ---
    // Consecutive tid -> consecutive r: conflict-free STS; global reads hit L1
    // lines repeatedly across the k sweep (each 128B line used 8x).
    for (int idx = tid; idx < Hd * RT; idx += 256) {
        int k = idx >> 6;      // 0..511 (4 k-values per 256-thread pass)
        int r = idx & 63;
        Ws[k * RT + r] = W_hh[(r0 + r) * Hd + k];
    }

    // Per-thread row parameters (fixed rows for whole run)
    float whx[4], bh[4];
#pragma unroll
    for (int i = 0; i < 4; ++i) {
        whx[i] = W_hx[r0 + ty4 + i];
        bh[i]  = b_h[r0 + ty4 + i];
    }

    // --- Zero h0 (buffer 0), partitioned across CTAs ---
    {
        float4 z = make_float4(0.f, 0.f, 0.f, 0.f);
        float4* hb = (float4*)g_h[0];
        int base = blockIdx.x * 1024;       // 131072 float4 total / 128 CTAs
#pragma unroll
        for (int p = 0; p < 4; ++p)
            hb[base + tid + p * 256] = z;
    }
    grid_barrier();

    int buf = 0;
    for (int t = 0; t < Td; ++t) {
        const float* __restrict__ hin  = g_h[buf];
        float* __restrict__       hout = g_h[buf ^ 1];

        if (tid < CT) xs[tid] = __ldg(&x[(c0 + tid) * Td + t]);

        float acc[4][4];
#pragma unroll
        for (int i = 0; i < 4; ++i)
#pragma unroll
            for (int j = 0; j < 4; ++j) acc[i][j] = 0.f;

        // Prefetch chunk 0 into registers (L2-only loads: h is cross-SM data)
        float4 pf[4];
#pragma unroll
        for (int p = 0; p < 4; ++p) {
            int f  = tid + p * 256;         // float4 index in chunk [64 x 16]
            int kk = f >> 4;
            int c4 = f & 15;
            pf[p] = __ldcg((const float4*)&hin[kk * Bd + c0 + c4 * 4]);
        }

        for (int c = 0; c < 8; ++c) {
            float* hsb = Hs + (c & 1) * (KC * CT);
#pragma unroll
            for (int p = 0; p < 4; ++p) {
                int f  = tid + p * 256;
                int kk = f >> 4;
                int c4 = f & 15;
                *(float4*)&hsb[kk * CT + c4 * 4] = pf[p];
            }
            __syncthreads();   // hsb ready; prior compute on this buffer finished 2 chunks ago

            if (c < 7) {
                int k0n = (c + 1) * KC;
#pragma unroll
                for (int p = 0; p < 4; ++p) {
                    int f  = tid + p * 256;
                    int kk = f >> 4;
                    int c4 = f & 15;
                    pf[p] = __ldcg((const float4*)&hin[(k0n + kk) * Bd + c0 + c4 * 4]);
                }
            }

            const float* wbase = Ws + (c * KC) * RT;
#pragma unroll 8
            for (int kk = 0; kk < KC; ++kk) {
                float4 wv = *(const float4*)&wbase[kk * RT + ty4];
                float4 hv = *(const float4*)&hsb[kk * CT + tx4];
                acc[0][0] += wv.x * hv.x;  acc[0][1] += wv.x * hv.y;
                acc[0][2] += wv.x * hv.z;  acc[0][3] += wv.x * hv.w;
                acc[1][0] += wv.y * hv.x;  acc[1][1] += wv.y * hv.y;
                acc[1][2] += wv.y * hv.z;  acc[1][3] += wv.y * hv.w;
                acc[2][0] += wv.z * hv.x;  acc[2][1] += wv.z * hv.y;
                acc[2][2] += wv.z * hv.z;  acc[2][3] += wv.z * hv.w;
                acc[3][0] += wv.w * hv.x;  acc[3][1] += wv.w * hv.y;
                acc[3][2] += wv.w * hv.z;  acc[3][3] += wv.w * hv.w;
            }
            // No second sync needed: next chunk's STS targets the other buffer.
        }

        // Epilogue: h_new = tanh(acc + W_hx[r]*x[b,t] + b_h[r]), write ping-pong buffer
        float xv0 = xs[tx4 + 0], xv1 = xs[tx4 + 1], xv2 = xs[tx4 + 2], xv3 = xs[tx4 + 3];
#pragma unroll
        for (int i = 0; i < 4; ++i) {
            int r = r0 + ty4 + i;
            float4 o;
            o.x = tanhf(acc[i][0] + whx[i] * xv0 + bh[i]);
            o.y = tanhf(acc[i][1] + whx[i] * xv1 + bh[i]);
            o.z = tanhf(acc[i][2] + whx[i] * xv2 + bh[i]);
            o.w = tanhf(acc[i][3] + whx[i] * xv3 + bh[i]);
            *(float4*)&hout[r * Bd + c0 + tx4] = o;
        }

        buf ^= 1;
        grid_barrier();   // publishes hout to all CTAs
    }

    // --- Final projection: out[b][o] = b_y[o] + sum_k W_yh[o][k] * h_T[k][b] ---
    // After 512 flips, final h is in g_h[buf] (buf == 0). Only rt==0 CTAs work.
    if (rt == 0) {
        const float* __restrict__ hf = g_h[buf];
        for (int idx = tid; idx < Od * CT; idx += 256) {
            int o  = idx >> 6;          // 0..9
            int cc = idx & 63;
            int b  = c0 + cc;
            float acc2 = b_y[o];
            const float* wrow = W_yh + o * Hd;
#pragma unroll 4
            for (int k = 0; k < Hd; ++k)
                acc2 += wrow[k] * __ldcg(&hf[k * Bd + b]);
            out[b * Od + o] = acc2;
        }
    }
}

extern "C" void kernel_launch(void* const* d_in, const int* in_sizes, int n_in,
                              void* d_out, int out_size) {
    (void)in_sizes; (void)n_in; (void)out_size;
    const float* x    = (const float*)d_in[0];
    const float* W_hx = (const float*)d_in[1];
    const float* W_hh = (const float*)d_in[2];
    const float* W_yh = (const float*)d_in[3];
    const float* b_h  = (const float*)d_in[4];
    const float* b_y  = (const float*)d_in[5];
    float* out = (float*)d_out;

    const int smem_bytes = (Hd * RT + 2 * KC * CT + CT) * (int)sizeof(float); // ~164 KB
    cudaFuncSetAttribute(rnn_persistent_kernel,
                         cudaFuncAttributeMaxDynamicSharedMemorySize, smem_bytes);

    rnn_persistent_kernel<<<NCTA, 256, smem_bytes>>>(x, W_hx, W_hh, W_yh, b_h, b_y, out);
}

// round 4
// speedup vs baseline: 2.2745x; 2.2659x over previous
#include <cuda_runtime.h>
#include <cuda_bf16.h>

#define Hn 512
#define Bn 1024
#define Tn 512
#define On 10
#define NCTA 128        // 8 hidden tiles x 16 batch tiles, 1 CTA/SM

// SMEM byte offsets
#define SM_WHI 0        // 8 chunks x [64 rows x 64 k] bf16 SW128 = 65536
#define SM_WLO 65536
#define SM_A   131072   // 4 bufs x (hi 8KB + lo 8KB) = 65536
#define SM_WB  196608   // float2[64] {W_hx[n], b_h[n]}
#define SM_XS  197120   // float[64] x values
#define SM_TOTAL 197376

__device__ __align__(16) __nv_bfloat16 g_hhi[2][Hn * Bn];  // [buf][k*Bn + b]
__device__ __align__(16) __nv_bfloat16 g_hlo[2][Hn * Bn];
__device__ unsigned g_bar_count = 0;
__device__ unsigned g_bar_gen   = 0;

static __device__ __forceinline__ unsigned smem_u32(const void* p) {
    unsigned a;
    asm("{ .reg .u64 t; cvta.to.shared.u64 t, %1; cvt.u32.u64 %0, t; }" : "=r"(a) : "l"(p));
    return a;
}
static __device__ __forceinline__ void cpa16(unsigned dst, const void* src) {
    asm volatile("cp.async.cg.shared.global [%0], [%1], 16;" :: "r"(dst), "l"(src));
}
#define CP_COMMIT() asm volatile("cp.async.commit_group;" ::: "memory")
#define CP_WAIT1()  asm volatile("cp.async.wait_group 1;" ::: "memory")
#define CP_WAIT0()  asm volatile("cp.async.wait_group 0;" ::: "memory")

static __device__ __forceinline__ void ldm4(unsigned* r, unsigned addr) {
    asm volatile("ldmatrix.sync.aligned.m8n8.x4.shared.b16 {%0,%1,%2,%3}, [%4];"
                 : "=r"(r[0]), "=r"(r[1]), "=r"(r[2]), "=r"(r[3]) : "r"(addr));
}
static __device__ __forceinline__ void ldm4t(unsigned* r, unsigned addr) {
    asm volatile("ldmatrix.sync.aligned.m8n8.x4.trans.shared.b16 {%0,%1,%2,%3}, [%4];"
                 : "=r"(r[0]), "=r"(r[1]), "=r"(r[2]), "=r"(r[3]) : "r"(addr));
}
static __device__ __forceinline__ void mma16816(float* d, const unsigned* a, const unsigned* b) {
    asm volatile("mma.sync.aligned.m16n8k16.row.col.f32.bf16.bf16.f32 "
                 "{%0,%1,%2,%3}, {%4,%5,%6,%7}, {%8,%9}, {%0,%1,%2,%3};"
                 : "+f"(d[0]), "+f"(d[1]), "+f"(d[2]), "+f"(d[3])
                 : "r"(a[0]), "r"(a[1]), "r"(a[2]), "r"(a[3]), "r"(b[0]), "r"(b[1]));
}

static __device__ __forceinline__ float fast_tanh(float v) {
    float e, r;
    asm("ex2.approx.f32 %0, %1;" : "=f"(e) : "f"(v * 2.885390081777927f)); // e^{2v}
    asm("rcp.approx.f32 %0, %1;" : "=f"(r) : "f"(e + 1.0f));
    return fmaf(-2.0f, r, 1.0f);
}
static __device__ __forceinline__ unsigned pack_bf2(__nv_bfloat16 a, __nv_bfloat16 b) {
    return (unsigned)__bfloat16_as_ushort(a) | ((unsigned)__bfloat16_as_ushort(b) << 16);
}

__device__ __forceinline__ void grid_barrier() {
    __syncthreads();
    __threadfence();
    if (threadIdx.x == 0) {
        unsigned gen = *((volatile unsigned*)&g_bar_gen);
        unsigned t = atomicAdd(&g_bar_count, 1u);
        if (t == NCTA - 1) {
            g_bar_count = 0;
            __threadfence();
            atomicAdd(&g_bar_gen, 1u);
        } else {
            while (*((volatile unsigned*)&g_bar_gen) == gen) { __nanosleep(16); }
        }
    }
    __syncthreads();
}

extern __shared__ char smem[];

__global__ void __launch_bounds__(256, 1)
rnn_hmma_kernel(const float* __restrict__ x,    const float* __restrict__ W_hx,
                const float* __restrict__ W_hh, const float* __restrict__ W_yh,
                const float* __restrict__ b_h,  const float* __restrict__ b_y,
                float* __restrict__ out)
{
    const unsigned sb = smem_u32(smem);
    const int tid  = threadIdx.x;
    const int lane = tid & 31;
    const int wid  = tid >> 5;
    const int nt   = blockIdx.x & 7;     // hidden tile 0..7
    const int ct   = blockIdx.x >> 3;    // batch tile 0..15
    const int n0   = nt * 64;
    const int c0   = ct * 64;
    const int wm   = wid & 1;            // warp M group (32 rows)
    const int wn   = wid >> 1;           // warp N group (16 batch)

    // ---- Stage W_hh rows n0..n0+63 as bf16 hi/lo: 8 SW128 chunks [64r x 64k] ----
    for (int idx = tid; idx < 64 * Hn; idx += 256) {
        int r = idx >> 9, k = idx & 511;
        float w = W_hh[(n0 + r) * Hn + k];
        __nv_bfloat16 whi = __float2bfloat16(w);
        __nv_bfloat16 wlo = __float2bfloat16(w - __bfloat162float(whi));
        int c = k >> 6, kc = k & 63;
        unsigned off = (unsigned)(r * 128 + kc * 2);
        unsigned sw  = off ^ ((off >> 3) & 0x70);
        *(__nv_bfloat16*)(smem + SM_WHI + c * 8192 + sw) = whi;
        *(__nv_bfloat16*)(smem + SM_WLO + c * 8192 + sw) = wlo;
    }
    if (tid < 64)
        ((float2*)(smem + SM_WB))[tid] = make_float2(W_hx[n0 + tid], b_h[n0 + tid]);

    // ---- Zero h0 (buffer 0); graph replays must re-zero ----
    {
        uint4 z = make_uint4(0, 0, 0, 0);
        int base = blockIdx.x * 512;
        uint4* p0 = (uint4*)g_hhi[0];
        uint4* p1 = (uint4*)g_hlo[0];
        p0[base + tid] = z; p0[base + 256 + tid] = z;
        p1[base + tid] = z; p1[base + 256 + tid] = z;
    }

    // ---- cp.async slot precompute: 4 x 16B per thread per chunk ----
    const char* s0[4]; const char* s1[4]; unsigned dsw[4];
#pragma unroll
    for (int j = 0; j < 4; ++j) {
        int f = j * 256 + tid;
        int arr = f >> 9;               // 0=hi 1=lo
        int ff = f & 511;
        int row = ff >> 3, seg = ff & 7;
        size_t so = (size_t)row * (Bn * 2) + seg * 16 + (size_t)c0 * 2;
        s0[j] = (const char*)(arr ? g_hlo[0] : g_hhi[0]) + so;
        s1[j] = (const char*)(arr ? g_hlo[1] : g_hhi[1]) + so;
        unsigned off = (unsigned)(row * 128 + seg * 16);
        dsw[j] = (unsigned)(arr * 8192) + (off ^ ((row & 7) << 4));
    }

    // ---- ldmatrix lane constants ----
    const int lane15 = lane & 15;
    const unsigned axor  = (unsigned)((lane & 7) << 4);
    const unsigned arow0 = (unsigned)((wm * 32 + lane15) * 128);       // mi=0 row base
    const unsigned acx   = ((unsigned)((lane >> 4) * 16)) ^ axor;      // A col ^ key
    const unsigned browb = (unsigned)(lane15 * 128);                   // B row base
    const unsigned bcx   = ((unsigned)(wn * 32 + (lane >> 4) * 16)) ^ axor;

    const float2* WB = (const float2*)(smem + SM_WB);
    float* XS = (float*)(smem + SM_XS);

    grid_barrier();   // h0 zeroed everywhere; W staging visible via entry __syncthreads

#define PREFETCH(ch, sp) do {                                     \
        unsigned db = sb + SM_A + (unsigned)(((ch) & 3) * 16384); \
        size_t go = (size_t)(ch) * 131072;                        \
        cpa16(db + dsw[0], (sp)[0] + go);                         \
        cpa16(db + dsw[1], (sp)[1] + go);                         \
        cpa16(db + dsw[2], (sp)[2] + go);                         \
        cpa16(db + dsw[3], (sp)[3] + go);                         \
        CP_COMMIT(); } while (0)

    for (int t = 0; t < Tn; ++t) {
        if (tid < 64) XS[tid] = x[(c0 + tid) * Tn + t];
        const char* const* sp = (t & 1) ? s1 : s0;
        PREFETCH(0, sp);
        PREFETCH(1, sp);

        float acc[2][2][4];
#pragma unroll
        for (int mi = 0; mi < 2; ++mi)
#pragma unroll
            for (int ni = 0; ni < 2; ++ni)
#pragma unroll
                for (int q = 0; q < 4; ++q) acc[mi][ni][q] = 0.f;

        for (int c = 0; c < 8; ++c) {
            if (c < 7) CP_WAIT1(); else CP_WAIT0();
            __syncthreads();

            unsigned whb = sb + SM_WHI + (unsigned)(c * 8192);
            unsigned wlb = whb + 65536;
            unsigned hb  = sb + SM_A + (unsigned)((c & 3) * 16384);

#pragma unroll
            for (int ks = 0; ks < 4; ++ks) {
                unsigned ah[2][4], al[2][4], bh[4], bl[4];
                unsigned colA = acx ^ (unsigned)(ks * 32);
                ldm4(ah[0], whb + arow0 + colA);
                ldm4(ah[1], whb + arow0 + 2048 + colA);
                ldm4(al[0], wlb + arow0 + colA);
                ldm4(al[1], wlb + arow0 + 2048 + colA);
                unsigned rB = hb + browb + (unsigned)(ks * 2048) + bcx;
                ldm4t(bh, rB);            // hi h
                ldm4t(bl, rB + 8192);     // lo h
#pragma unroll
                for (int mi = 0; mi < 2; ++mi)
#pragma unroll
                    for (int ni = 0; ni < 2; ++ni) {
                        mma16816(acc[mi][ni], ah[mi], bh + ni * 2);
                        mma16816(acc[mi][ni], ah[mi], bl + ni * 2);
                        mma16816(acc[mi][ni], al[mi], bh + ni * 2);
                    }
            }
            if (c < 6) PREFETCH(c + 2, sp);
        }

        // ---- Epilogue: tanh + bf16 hi/lo split + store to ping-pong buffer ----
        int ob = (t + 1) & 1;
        __nv_bfloat16* oh = g_hhi[ob];
        __nv_bfloat16* ol = g_hlo[ob];
#pragma unroll
        for (int mi = 0; mi < 2; ++mi) {
            int rA = wm * 32 + mi * 16 + (lane >> 2);     // local hidden row
            float2 wA = WB[rA];
            float2 wB2 = WB[rA + 8];
#pragma unroll
            for (int ni = 0; ni < 2; ++ni) {
                int bl0 = wn * 16 + ni * 8 + 2 * (lane & 3);
                float xb0 = XS[bl0], xb1 = XS[bl0 + 1];
                float* a = acc[mi][ni];
                float y00 = fast_tanh(fmaf(wA.x,  xb0, a[0] + wA.y));
                float y01 = fast_tanh(fmaf(wA.x,  xb1, a[1] + wA.y));
                float y10 = fast_tanh(fmaf(wB2.x, xb0, a[2] + wB2.y));
                float y11 = fast_tanh(fmaf(wB2.x, xb1, a[3] + wB2.y));
                __nv_bfloat16 h00 = __float2bfloat16(y00), h01 = __float2bfloat16(y01);
                __nv_bfloat16 h10 = __float2bfloat16(y10), h11 = __float2bfloat16(y11);
                size_t o0 = (size_t)(n0 + rA) * Bn + (c0 + bl0);
                size_t o1 = o0 + (size_t)8 * Bn;
                *(unsigned*)(oh + o0) = pack_bf2(h00, h01);
                *(unsigned*)(ol + o0) = pack_bf2(__float2bfloat16(y00 - __bfloat162float(h00)),
                                                 __float2bfloat16(y01 - __bfloat162float(h01)));
                *(unsigned*)(oh + o1) = pack_bf2(h10, h11);
                *(unsigned*)(ol + o1) = pack_bf2(__float2bfloat16(y10 - __bfloat162float(h10)),
                                                 __float2bfloat16(y11 - __bfloat162float(h11)));
            }
        }
        grid_barrier();
    }

    // ---- Final projection: out[b][o] = b_y[o] + sum_k W_yh[o][k] * h[k][b] ----
    // Final h is in buffer 0 (t=511 wrote (511+1)&1 = 0).
    if (nt == 0) {
        // stage W_yh (10x512 f32 = 20KB) into SMEM (reuse W region; main loop done)
        float* Wy = (float*)(smem + SM_WHI);
        for (int idx = tid; idx < On * Hn; idx += 256) Wy[idx] = W_yh[idx];
        __syncthreads();
        if (tid < 64) {
            int b = c0 + tid;
            float a10[On];
#pragma unroll
            for (int o = 0; o < On; ++o) a10[o] = b_y[o];
            const __nv_bfloat16* hh = g_hhi[0];
            const __nv_bfloat16* hl = g_hlo[0];
            for (int k = 0; k < Hn; ++k) {
                float hv = __bfloat162float(__ldcg(hh + (size_t)k * Bn + b))
                         + __bfloat162float(__ldcg(hl + (size_t)k * Bn + b));
#pragma unroll
                for (int o = 0; o < On; ++o) a10[o] = fmaf(Wy[o * Hn + k], hv, a10[o]);
            }
#pragma unroll
            for (int o = 0; o < On; ++o) out[b * On + o] = a10[o];
        }
    }
}

extern "C" void kernel_launch(void* const* d_in, const int* in_sizes, int n_in,
                              void* d_out, int out_size) {
    (void)in_sizes; (void)n_in; (void)out_size;
    const float* x    = (const float*)d_in[0];
    const float* W_hx = (const float*)d_in[1];
    const float* W_hh = (const float*)d_in[2];
    const float* W_yh = (const float*)d_in[3];
    const float* b_h  = (const float*)d_in[4];
    const float* b_y  = (const float*)d_in[5];
    float* out = (float*)d_out;

    cudaFuncSetAttribute(rnn_hmma_kernel, cudaFuncAttributeMaxDynamicSharedMemorySize, SM_TOTAL);
    rnn_hmma_kernel<<<NCTA, 256, SM_TOTAL>>>(x, W_hx, W_hh, W_yh, b_h, b_y, out);
}